// round 11
// baseline (speedup 1.0000x reference)
#include <cuda_runtime.h>
#include <cuda_bf16.h>
#include <cstdint>

// Problem dims (fixed): B=1, S=128, L=256, D=256, H=8, C=32
#define S_ 128
#define L_ 256
#define D_ 256
#define H_ 8
#define C_ 32
#define MROWS (S_ * L_)          // 32768
#define LOG2E 1.4426950408889634f
#define NEG_BIAS2 (-10000.0f * LOG2E)
#define QSCALE (0.17677669529663687f * LOG2E)  // (1/sqrt(32)) * log2(e)

// ---------------- scratch (device globals; no cudaMalloc allowed) ----------
__device__ __nv_bfloat16 g_mnh[MROWS * D_];
__device__ __nv_bfloat16 g_mnl[MROWS * D_];
__device__ __nv_bfloat16 g_wh[5 * D_ * D_];   // [Wq|Wk|Wv|Wg|Wo] hi
__device__ __nv_bfloat16 g_wl[5 * D_ * D_];   // lo
__device__ float g_q[MROWS * D_];    // [s][h][l][c], pre-scaled by QSCALE
__device__ float g_k[MROWS * D_];
__device__ float g_v[MROWS * D_];
__device__ float g_g[MROWS * D_];
__device__ __nv_bfloat16 g_oh[MROWS * D_];    // attn out hi, [s][l][h*32+c]
__device__ __nv_bfloat16 g_ol[MROWS * D_];
__device__ float g_sp[L_];
__device__ float g_rp[L_];

__device__ __forceinline__ float fast_exp2(float x) {
    float y;
    asm("ex2.approx.ftz.f32 %0, %1;" : "=f"(y) : "f"(x));
    return y;
}
__device__ __forceinline__ uint32_t smem_u32(const void* p) {
    uint32_t a;
    asm("{ .reg .u64 t; cvta.to.shared.u64 t, %1; cvt.u32.u64 %0, t; }" : "=r"(a) : "l"(p));
    return a;
}
__device__ __forceinline__ void ldsm4(uint32_t* r, uint32_t addr) {
    asm volatile("ldmatrix.sync.aligned.m8n8.x4.shared.b16 {%0,%1,%2,%3}, [%4];"
                 : "=r"(r[0]), "=r"(r[1]), "=r"(r[2]), "=r"(r[3]) : "r"(addr));
}
__device__ __forceinline__ void mma_bf16(float* c, const uint32_t* a, uint32_t b0,
                                         uint32_t b1) {
    asm volatile(
        "mma.sync.aligned.m16n8k16.row.col.f32.bf16.bf16.f32 "
        "{%0,%1,%2,%3}, {%4,%5,%6,%7}, {%8,%9}, {%0,%1,%2,%3};"
        : "+f"(c[0]), "+f"(c[1]), "+f"(c[2]), "+f"(c[3])
        : "r"(a[0]), "r"(a[1]), "r"(a[2]), "r"(a[3]), "r"(b0), "r"(b1));
}
__device__ __forceinline__ void cp16(uint32_t smaddr, const void* gptr) {
    asm volatile("cp.async.cg.shared.global [%0], [%1], 16;" :: "r"(smaddr), "l"(gptr));
}
#define CP_COMMIT() asm volatile("cp.async.commit_group;" ::: "memory")
#define CP_WAIT0()  asm volatile("cp.async.wait_group 0;" ::: "memory")

// ---------------- mask prep: dtype-agnostic (bool8 / int32 / float32) ------
__global__ void prep_mask_kernel(const void* sp_raw, const void* rp_raw) {
    __shared__ int flagF, flagOff;
    int tid = threadIdx.x;  // 256
    if (tid == 0) { flagF = 0; flagOff = 0; }
    __syncthreads();
    const unsigned char* pb = (const unsigned char*)sp_raw;
    const unsigned char* qb = (const unsigned char*)rp_raw;
    unsigned char b1 = pb[tid], b2 = qb[tid];
    if ((tid & 3) == 3 && (b1 == 0x3F || b2 == 0x3F)) atomicOr(&flagF, 1);
    if ((tid & 3) != 0 && (b1 != 0 || b2 != 0)) atomicOr(&flagOff, 1);
    __syncthreads();
    int mode = flagF ? 2 : (flagOff ? 0 : 1);
    float vs, vr;
    if (mode == 0) {
        vs = (((const unsigned char*)sp_raw)[tid] != 0) ? 1.f : 0.f;
        vr = (((const unsigned char*)rp_raw)[tid] != 0) ? 1.f : 0.f;
    } else if (mode == 1) {
        vs = (((const int*)sp_raw)[tid] != 0) ? 1.f : 0.f;
        vr = (((const int*)rp_raw)[tid] != 0) ? 1.f : 0.f;
    } else {
        vs = (((const float*)sp_raw)[tid] != 0.f) ? 1.f : 0.f;
        vr = (((const float*)rp_raw)[tid] != 0.f) ? 1.f : 0.f;
    }
    g_sp[tid] = vs;
    g_rp[tid] = vr;
}

// ---------------- weight prep: fp32 -> bf16 hi/lo --------------------------
__global__ __launch_bounds__(256) void prep_w_kernel(
    const float* __restrict__ Wq, const float* __restrict__ Wk,
    const float* __restrict__ Wv, const float* __restrict__ Wg,
    const float* __restrict__ Wo) {
    int row = blockIdx.x;      // 0..1279
    int tid = threadIdx.x;
    int t = row >> 8;
    const float* W = (t == 0) ? Wq : (t == 1) ? Wk : (t == 2) ? Wv : (t == 3) ? Wg : Wo;
    float v = W[(size_t)(row & 255) * D_ + tid];
    __nv_bfloat16 hi = __float2bfloat16(v);
    __nv_bfloat16 lo = __float2bfloat16(v - __bfloat162float(hi));
    g_wh[(size_t)row * D_ + tid] = hi;
    g_wl[(size_t)row * D_ + tid] = lo;
}

// ---------------- LayerNorm: warp per row -> bf16 hi/lo --------------------
__global__ __launch_bounds__(256) void ln_kernel(const float* __restrict__ m,
                                                 const float* __restrict__ gam,
                                                 const float* __restrict__ bet) {
    int row = blockIdx.x * 8 + (threadIdx.x >> 5);
    int lane = threadIdx.x & 31;
    const float4* src = (const float4*)(m + (size_t)row * D_);
    float4 a = src[lane], b = src[lane + 32];
    float s1 = a.x + a.y + a.z + a.w + b.x + b.y + b.z + b.w;
    float s2 = a.x * a.x + a.y * a.y + a.z * a.z + a.w * a.w +
               b.x * b.x + b.y * b.y + b.z * b.z + b.w * b.w;
    #pragma unroll
    for (int o = 16; o > 0; o >>= 1) {
        s1 += __shfl_xor_sync(0xFFFFFFFFu, s1, o);
        s2 += __shfl_xor_sync(0xFFFFFFFFu, s2, o);
    }
    float mu = s1 * (1.f / D_);
    float rstd = rsqrtf(s2 * (1.f / D_) - mu * mu + 1e-5f);
    float va[8] = {a.x, a.y, a.z, a.w, b.x, b.y, b.z, b.w};
    #pragma unroll
    for (int i = 0; i < 8; i++) {
        int c = (i < 4) ? (lane * 4 + i) : (128 + lane * 4 + i - 4);
        float y = (va[i] - mu) * rstd * gam[c] + bet[c];
        __nv_bfloat16 hi = __float2bfloat16(y);
        __nv_bfloat16 lo = __float2bfloat16(y - __bfloat162float(hi));
        g_mnh[(size_t)row * D_ + c] = hi;
        g_mnl[(size_t)row * D_ + c] = lo;
    }
}

// ---------------- mma.sync GEMM: C[128x64] = A[128x256] * B[64x256]^T ------
// bf16x3: hi*hi + hi*lo + lo*hi, fp32 accumulators. Fragments loaded ONCE per
// k16 step, all 3 passes run from registers. Warps tiled 4m x 2n (32x32 each).
// 2 CTAs/SM via __launch_bounds__(256,2); cp.async.cg smem fills.
#define PADK 72
#define OFF_AH 0
#define OFF_AL (128 * PADK)
#define OFF_BH (2 * 128 * PADK)
#define OFF_BL (2 * 128 * PADK + 64 * PADK)
#define SM_GEMM_HALVES (2 * 128 * PADK + 2 * 64 * PADK)   // 27648 halves = 55296 B

__global__ __launch_bounds__(256, 2) void gemm_kernel(
    const __nv_bfloat16* __restrict__ Ah, const __nv_bfloat16* __restrict__ Al,
    const __nv_bfloat16* __restrict__ Bh, const __nv_bfloat16* __restrict__ Bl,
    const float* __restrict__ bias, float* __restrict__ outp, int mode) {
    extern __shared__ __align__(16) __nv_bfloat16 sm[];
    uint32_t smb = smem_u32(sm);
    int tid = threadIdx.x;
    int wid = tid >> 5, lane = tid & 31;
    int wm = wid & 3, wn = wid >> 2;
    int bm = blockIdx.y * 128;
    int bn0 = blockIdx.x * 64;

    const __nv_bfloat16* A0 = Ah + (size_t)bm * D_;
    const __nv_bfloat16* A1 = Al + (size_t)bm * D_;
    const __nv_bfloat16* B0 = Bh + (size_t)bn0 * D_;
    const __nv_bfloat16* B1 = Bl + (size_t)bn0 * D_;

    float acc[2][4][4];
    #pragma unroll
    for (int i = 0; i < 2; i++)
        #pragma unroll
        for (int f = 0; f < 4; f++)
            #pragma unroll
            for (int e = 0; e < 4; e++) acc[i][f][e] = 0.f;

    uint32_t aKof = (lane >> 4) * 8;
    uint32_t bN = (lane & 7) + ((lane >> 4) << 3);
    uint32_t bKof = ((lane >> 3) & 1) * 8;

    for (int k0 = 0; k0 < D_; k0 += 64) {
        if (k0) __syncthreads();   // prior chunk's reads done before overwrite
        // fill: A 128x64 hi+lo (1024 x 16B each), B 64x64 hi+lo (512 each)
        #pragma unroll
        for (int t = 0; t < 4; t++) {
            int i = tid + t * 256;
            int r = i >> 3, sg = i & 7;
            uint32_t d = smb + (uint32_t)(r * PADK + sg * 8) * 2;
            const __nv_bfloat16* s = A0 + (size_t)r * D_ + k0 + sg * 8;
            cp16(d + OFF_AH * 2, s);
            cp16(d + OFF_AL * 2, A1 + (s - A0));
        }
        #pragma unroll
        for (int t = 0; t < 2; t++) {
            int i = tid + t * 256;
            int r = i >> 3, sg = i & 7;
            uint32_t d = smb + (uint32_t)(r * PADK + sg * 8) * 2;
            const __nv_bfloat16* s = B0 + (size_t)r * D_ + k0 + sg * 8;
            cp16(d + OFF_BH * 2, s);
            cp16(d + OFF_BL * 2, B1 + (s - B0));
        }
        CP_COMMIT();
        CP_WAIT0();
        __syncthreads();

        #pragma unroll
        for (int ks = 0; ks < 4; ks++) {
            uint32_t ah[2][4], al[2][4], bh[2][4], bl[2][4];
            #pragma unroll
            for (int mf = 0; mf < 2; mf++) {
                uint32_t r = wm * 32 + mf * 16 + (lane & 15);
                uint32_t off = (r * PADK + ks * 16 + aKof) * 2;
                ldsm4(ah[mf], smb + OFF_AH * 2 + off);
                ldsm4(al[mf], smb + OFF_AL * 2 + off);
            }
            #pragma unroll
            for (int bf = 0; bf < 2; bf++) {
                uint32_t r = wn * 32 + bf * 16 + bN;
                uint32_t off = (r * PADK + ks * 16 + bKof) * 2;
                ldsm4(bh[bf], smb + OFF_BH * 2 + off);
                ldsm4(bl[bf], smb + OFF_BL * 2 + off);
            }
            #pragma unroll
            for (int mf = 0; mf < 2; mf++)
                #pragma unroll
                for (int bf = 0; bf < 2; bf++) {
                    mma_bf16(acc[mf][bf * 2 + 0], ah[mf], bh[bf][0], bh[bf][1]);
                    mma_bf16(acc[mf][bf * 2 + 1], ah[mf], bh[bf][2], bh[bf][3]);
                    mma_bf16(acc[mf][bf * 2 + 0], ah[mf], bl[bf][0], bl[bf][1]);
                    mma_bf16(acc[mf][bf * 2 + 1], ah[mf], bl[bf][2], bl[bf][3]);
                    mma_bf16(acc[mf][bf * 2 + 0], al[mf], bh[bf][0], bh[bf][1]);
                    mma_bf16(acc[mf][bf * 2 + 1], al[mf], bh[bf][2], bh[bf][3]);
                }
        }
    }

    // --- epilogue: scatter directly from fragments
    if (mode == 0) {
        int t = bn0 >> 8;
        #pragma unroll
        for (int mf = 0; mf < 2; mf++)
            #pragma unroll
            for (int f = 0; f < 4; f++) {
                int bf = f >> 1, half = f & 1;
                #pragma unroll
                for (int e = 0; e < 4; e++) {
                    int rr = bm + wm * 32 + mf * 16 + (lane >> 2) + (e >> 1) * 8;
                    int cc = bn0 + wn * 32 + bf * 16 + half * 8 + (lane & 3) * 2 + (e & 1);
                    int s = rr >> 8, l = rr & 255;
                    int jj = cc & 255;
                    int h = jj >> 5, ch = jj & 31;
                    size_t dst = (((size_t)(s * H_ + h) * L_) + l) * C_ + ch;
                    float v = acc[mf][f][e];
                    if (t == 0)      g_q[dst] = v * QSCALE;
                    else if (t == 1) g_k[dst] = v;
                    else if (t == 2) g_v[dst] = v;
                    else             g_g[dst] = 1.f / (1.f + fast_exp2(-(v + bias[jj]) * LOG2E));
                }
            }
    } else {
        #pragma unroll
        for (int mf = 0; mf < 2; mf++)
            #pragma unroll
            for (int f = 0; f < 4; f++) {
                int bf = f >> 1, half = f & 1;
                #pragma unroll
                for (int e = 0; e < 4; e++) {
                    int rr = bm + wm * 32 + mf * 16 + (lane >> 2) + (e >> 1) * 8;
                    int cc = bn0 + wn * 32 + bf * 16 + half * 8 + (lane & 3) * 2 + (e & 1);
                    outp[(size_t)rr * D_ + cc] = acc[mf][f][e] + bias[cc];
                }
            }
    }
}

// ---------------- Attention: one block per (s,h), max-free softmax ---------
// float4 smem loads: 16 LDS.128 per key instead of 64 scalar LDS.
__global__ __launch_bounds__(256) void attn_kernel() {
    extern __shared__ float smem[];
    float* ks = smem;
    float* vs = smem + L_ * C_;
    float* bcol = smem + 2 * L_ * C_;
    int sh = blockIdx.x;
    int s = sh >> 3, h = sh & 7;
    size_t base = (size_t)sh * (L_ * C_);
    int tid = threadIdx.x;

    for (int i = tid; i < L_ * C_ / 4; i += 256) {
        ((float4*)ks)[i] = ((const float4*)(g_k + base))[i];
        ((float4*)vs)[i] = ((const float4*)(g_v + base))[i];
    }
    bcol[tid] = (g_rp[tid] != 0.f) ? NEG_BIAS2 : 0.f;
    __syncthreads();

    int l = tid;
    float4 q4[8];
    const float4* qsrc = (const float4*)(g_q + base + (size_t)l * C_);
    #pragma unroll
    for (int c = 0; c < 8; c++) q4[c] = qsrc[c];
    bool rowm = (g_sp[l] != 0.f);

    float ssum = 0.f;
    float4 acc[8];
    #pragma unroll
    for (int c = 0; c < 8; c++) acc[c] = make_float4(0.f, 0.f, 0.f, 0.f);

    for (int j = 0; j < L_; j++) {
        const float4* kr = (const float4*)(ks + j * C_);
        float s0 = 0.f, s1 = 0.f, s2 = 0.f, s3 = 0.f;
        #pragma unroll
        for (int c = 0; c < 8; c++) {
            float4 kv = kr[c];
            s0 = fmaf(q4[c].x, kv.x, s0);
            s1 = fmaf(q4[c].y, kv.y, s1);
            s2 = fmaf(q4[c].z, kv.z, s2);
            s3 = fmaf(q4[c].w, kv.w, s3);
        }
        float sc = (s0 + s1) + (s2 + s3);
        if (!rowm) sc += bcol[j];
        float p = fast_exp2(sc);
        ssum += p;
        const float4* vr = (const float4*)(vs + j * C_);
        #pragma unroll
        for (int c = 0; c < 8; c++) {
            float4 vv = vr[c];
            acc[c].x = fmaf(p, vv.x, acc[c].x);
            acc[c].y = fmaf(p, vv.y, acc[c].y);
            acc[c].z = fmaf(p, vv.z, acc[c].z);
            acc[c].w = fmaf(p, vv.w, acc[c].w);
        }
    }

    float inv = 1.f / ssum;
    size_t obase = ((size_t)(s * L_ + l)) * D_ + h * C_;
    size_t gbase = base + (size_t)l * C_;
    #pragma unroll
    for (int c = 0; c < 8; c++) {
        float o[4] = {acc[c].x, acc[c].y, acc[c].z, acc[c].w};
        #pragma unroll
        for (int e = 0; e < 4; e++) {
            float ov = o[e] * inv * g_g[gbase + c * 4 + e];
            __nv_bfloat16 hi = __float2bfloat16(ov);
            __nv_bfloat16 lo = __float2bfloat16(ov - __bfloat162float(hi));
            g_oh[obase + c * 4 + e] = hi;
            g_ol[obase + c * 4 + e] = lo;
        }
    }
}

// ---------------- launch ---------------------------------------------------
extern "C" void kernel_launch(void* const* d_in, const int* in_sizes, int n_in,
                              void* d_out, int out_size) {
    const float* m    = (const float*)d_in[0];
    const void*  spad = d_in[1];
    const void*  rpad = d_in[2];
    const float* ln_g = (const float*)d_in[3];
    const float* ln_b = (const float*)d_in[4];
    const float* Wq   = (const float*)d_in[5];
    const float* Wk   = (const float*)d_in[6];
    const float* Wv   = (const float*)d_in[7];
    const float* Wg   = (const float*)d_in[8];
    const float* bg   = (const float*)d_in[9];
    const float* Wo   = (const float*)d_in[10];
    const float* bo   = (const float*)d_in[11];
    float* out = (float*)d_out;

    static int smem_set = 0;
    if (!smem_set) {
        cudaFuncSetAttribute(gemm_kernel, cudaFuncAttributeMaxDynamicSharedMemorySize,
                             SM_GEMM_HALVES * 2);
        cudaFuncSetAttribute(attn_kernel, cudaFuncAttributeMaxDynamicSharedMemorySize,
                             (2 * L_ * C_ + L_) * (int)sizeof(float));
        smem_set = 1;
    }

    prep_mask_kernel<<<1, 256>>>(spad, rpad);
    prep_w_kernel<<<5 * 256, 256>>>(Wq, Wk, Wv, Wg, Wo);
    ln_kernel<<<MROWS / 8, 256>>>(m, ln_g, ln_b);

    __nv_bfloat16 *mh, *ml, *wh, *wl, *oh, *ol;
    cudaGetSymbolAddress((void**)&mh, g_mnh);
    cudaGetSymbolAddress((void**)&ml, g_mnl);
    cudaGetSymbolAddress((void**)&wh, g_wh);
    cudaGetSymbolAddress((void**)&wl, g_wl);
    cudaGetSymbolAddress((void**)&oh, g_oh);
    cudaGetSymbolAddress((void**)&ol, g_ol);

    dim3 gp(16, MROWS / 128);   // proj: N = [Wq|Wk|Wv|Wg]
    gemm_kernel<<<gp, 256, SM_GEMM_HALVES * 2>>>(mh, ml, wh, wl, bg, nullptr, 0);

    int attn_smem = (2 * L_ * C_ + L_) * (int)sizeof(float);
    attn_kernel<<<S_ * H_, 256, attn_smem>>>();

    dim3 go(4, MROWS / 128);    // out projection
    gemm_kernel<<<go, 256, SM_GEMM_HALVES * 2>>>(oh, ol, wh + 4 * D_ * D_,
                                                 wl + 4 * D_ * D_, bo, out, 1);
}

// round 12
// speedup vs baseline: 1.0019x; 1.0019x over previous
#include <cuda_runtime.h>
#include <cuda_bf16.h>
#include <cstdint>

// Problem dims (fixed): B=1, S=128, L=256, D=256, H=8, C=32
#define S_ 128
#define L_ 256
#define D_ 256
#define H_ 8
#define C_ 32
#define MROWS (S_ * L_)          // 32768
#define LOG2E 1.4426950408889634f
#define NEG_BIAS2 (-10000.0f * LOG2E)
#define QSCALE (0.17677669529663687f * LOG2E)  // (1/sqrt(32)) * log2(e)

// ---------------- scratch (device globals; no cudaMalloc allowed) ----------
__device__ __nv_bfloat16 g_mnh[MROWS * D_];
__device__ __nv_bfloat16 g_mnl[MROWS * D_];
__device__ __nv_bfloat16 g_wh[5 * D_ * D_];   // [Wq|Wk|Wv|Wg|Wo] hi
__device__ __nv_bfloat16 g_wl[5 * D_ * D_];   // lo
__device__ float g_q[MROWS * D_];    // [s][h][l][c], pre-scaled by QSCALE
__device__ float g_k[MROWS * D_];
__device__ float g_v[MROWS * D_];
__device__ float g_g[MROWS * D_];
__device__ __nv_bfloat16 g_oh[MROWS * D_];    // attn out hi, [s][l][h*32+c]
__device__ __nv_bfloat16 g_ol[MROWS * D_];
__device__ float g_sp[L_];
__device__ float g_rp[L_];

__device__ __forceinline__ float fast_exp2(float x) {
    float y;
    asm("ex2.approx.ftz.f32 %0, %1;" : "=f"(y) : "f"(x));
    return y;
}
__device__ __forceinline__ uint32_t smem_u32(const void* p) {
    uint32_t a;
    asm("{ .reg .u64 t; cvta.to.shared.u64 t, %1; cvt.u32.u64 %0, t; }" : "=r"(a) : "l"(p));
    return a;
}
__device__ __forceinline__ void ldsm4(uint32_t* r, uint32_t addr) {
    asm volatile("ldmatrix.sync.aligned.m8n8.x4.shared.b16 {%0,%1,%2,%3}, [%4];"
                 : "=r"(r[0]), "=r"(r[1]), "=r"(r[2]), "=r"(r[3]) : "r"(addr));
}
__device__ __forceinline__ void mma_bf16(float* c, const uint32_t* a, uint32_t b0,
                                         uint32_t b1) {
    asm volatile(
        "mma.sync.aligned.m16n8k16.row.col.f32.bf16.bf16.f32 "
        "{%0,%1,%2,%3}, {%4,%5,%6,%7}, {%8,%9}, {%0,%1,%2,%3};"
        : "+f"(c[0]), "+f"(c[1]), "+f"(c[2]), "+f"(c[3])
        : "r"(a[0]), "r"(a[1]), "r"(a[2]), "r"(a[3]), "r"(b0), "r"(b1));
}
__device__ __forceinline__ void cp16(uint32_t smaddr, const void* gptr) {
    asm volatile("cp.async.cg.shared.global [%0], [%1], 16;" :: "r"(smaddr), "l"(gptr));
}
#define CP_COMMIT() asm volatile("cp.async.commit_group;" ::: "memory")
#define CP_WAIT0()  asm volatile("cp.async.wait_group 0;" ::: "memory")

// ---------------- mask prep: dtype-agnostic (bool8 / int32 / float32) ------
__global__ void prep_mask_kernel(const void* sp_raw, const void* rp_raw) {
    __shared__ int flagF, flagOff;
    int tid = threadIdx.x;  // 256
    if (tid == 0) { flagF = 0; flagOff = 0; }
    __syncthreads();
    const unsigned char* pb = (const unsigned char*)sp_raw;
    const unsigned char* qb = (const unsigned char*)rp_raw;
    unsigned char b1 = pb[tid], b2 = qb[tid];
    if ((tid & 3) == 3 && (b1 == 0x3F || b2 == 0x3F)) atomicOr(&flagF, 1);
    if ((tid & 3) != 0 && (b1 != 0 || b2 != 0)) atomicOr(&flagOff, 1);
    __syncthreads();
    int mode = flagF ? 2 : (flagOff ? 0 : 1);
    float vs, vr;
    if (mode == 0) {
        vs = (((const unsigned char*)sp_raw)[tid] != 0) ? 1.f : 0.f;
        vr = (((const unsigned char*)rp_raw)[tid] != 0) ? 1.f : 0.f;
    } else if (mode == 1) {
        vs = (((const int*)sp_raw)[tid] != 0) ? 1.f : 0.f;
        vr = (((const int*)rp_raw)[tid] != 0) ? 1.f : 0.f;
    } else {
        vs = (((const float*)sp_raw)[tid] != 0.f) ? 1.f : 0.f;
        vr = (((const float*)rp_raw)[tid] != 0.f) ? 1.f : 0.f;
    }
    g_sp[tid] = vs;
    g_rp[tid] = vr;
}

// ---------------- weight prep: fp32 -> bf16 hi/lo --------------------------
__global__ __launch_bounds__(256) void prep_w_kernel(
    const float* __restrict__ Wq, const float* __restrict__ Wk,
    const float* __restrict__ Wv, const float* __restrict__ Wg,
    const float* __restrict__ Wo) {
    int row = blockIdx.x;      // 0..1279
    int tid = threadIdx.x;
    int t = row >> 8;
    const float* W = (t == 0) ? Wq : (t == 1) ? Wk : (t == 2) ? Wv : (t == 3) ? Wg : Wo;
    float v = W[(size_t)(row & 255) * D_ + tid];
    __nv_bfloat16 hi = __float2bfloat16(v);
    __nv_bfloat16 lo = __float2bfloat16(v - __bfloat162float(hi));
    g_wh[(size_t)row * D_ + tid] = hi;
    g_wl[(size_t)row * D_ + tid] = lo;
}

// ---------------- LayerNorm: warp per row -> bf16 hi/lo --------------------
__global__ __launch_bounds__(256) void ln_kernel(const float* __restrict__ m,
                                                 const float* __restrict__ gam,
                                                 const float* __restrict__ bet) {
    int row = blockIdx.x * 8 + (threadIdx.x >> 5);
    int lane = threadIdx.x & 31;
    const float4* src = (const float4*)(m + (size_t)row * D_);
    float4 a = src[lane], b = src[lane + 32];
    float s1 = a.x + a.y + a.z + a.w + b.x + b.y + b.z + b.w;
    float s2 = a.x * a.x + a.y * a.y + a.z * a.z + a.w * a.w +
               b.x * b.x + b.y * b.y + b.z * b.z + b.w * b.w;
    #pragma unroll
    for (int o = 16; o > 0; o >>= 1) {
        s1 += __shfl_xor_sync(0xFFFFFFFFu, s1, o);
        s2 += __shfl_xor_sync(0xFFFFFFFFu, s2, o);
    }
    float mu = s1 * (1.f / D_);
    float rstd = rsqrtf(s2 * (1.f / D_) - mu * mu + 1e-5f);
    float va[8] = {a.x, a.y, a.z, a.w, b.x, b.y, b.z, b.w};
    #pragma unroll
    for (int i = 0; i < 8; i++) {
        int c = (i < 4) ? (lane * 4 + i) : (128 + lane * 4 + i - 4);
        float y = (va[i] - mu) * rstd * gam[c] + bet[c];
        __nv_bfloat16 hi = __float2bfloat16(y);
        __nv_bfloat16 lo = __float2bfloat16(y - __bfloat162float(hi));
        g_mnh[(size_t)row * D_ + c] = hi;
        g_mnl[(size_t)row * D_ + c] = lo;
    }
}

// ---------------- mma.sync GEMM: C[128x64] = A[128x256] * B[64x256]^T ------
// bf16x3: hi*hi + hi*lo + lo*hi, fp32 accumulators. Fragments loaded ONCE per
// k16 step, all 3 passes run from registers. Warps tiled 4m x 2n (32x32 each).
// 2 CTAs/SM via __launch_bounds__(256,2); cp.async.cg smem fills.
#define PADK 72
#define OFF_AH 0
#define OFF_AL (128 * PADK)
#define OFF_BH (2 * 128 * PADK)
#define OFF_BL (2 * 128 * PADK + 64 * PADK)
#define SM_GEMM_HALVES (2 * 128 * PADK + 2 * 64 * PADK)   // 27648 halves = 55296 B

__global__ __launch_bounds__(256, 2) void gemm_kernel(
    const __nv_bfloat16* __restrict__ Ah, const __nv_bfloat16* __restrict__ Al,
    const __nv_bfloat16* __restrict__ Bh, const __nv_bfloat16* __restrict__ Bl,
    const float* __restrict__ bias, float* __restrict__ outp, int mode) {
    extern __shared__ __align__(16) __nv_bfloat16 sm[];
    uint32_t smb = smem_u32(sm);
    int tid = threadIdx.x;
    int wid = tid >> 5, lane = tid & 31;
    int wm = wid & 3, wn = wid >> 2;
    int bm = blockIdx.y * 128;
    int bn0 = blockIdx.x * 64;

    const __nv_bfloat16* A0 = Ah + (size_t)bm * D_;
    const __nv_bfloat16* A1 = Al + (size_t)bm * D_;
    const __nv_bfloat16* B0 = Bh + (size_t)bn0 * D_;
    const __nv_bfloat16* B1 = Bl + (size_t)bn0 * D_;

    float acc[2][4][4];
    #pragma unroll
    for (int i = 0; i < 2; i++)
        #pragma unroll
        for (int f = 0; f < 4; f++)
            #pragma unroll
            for (int e = 0; e < 4; e++) acc[i][f][e] = 0.f;

    uint32_t aKof = (lane >> 4) * 8;
    uint32_t bN = (lane & 7) + ((lane >> 4) << 3);
    uint32_t bKof = ((lane >> 3) & 1) * 8;

    for (int k0 = 0; k0 < D_; k0 += 64) {
        if (k0) __syncthreads();   // prior chunk's reads done before overwrite
        // fill: A 128x64 hi+lo (1024 x 16B each), B 64x64 hi+lo (512 each)
        #pragma unroll
        for (int t = 0; t < 4; t++) {
            int i = tid + t * 256;
            int r = i >> 3, sg = i & 7;
            uint32_t d = smb + (uint32_t)(r * PADK + sg * 8) * 2;
            const __nv_bfloat16* s = A0 + (size_t)r * D_ + k0 + sg * 8;
            cp16(d + OFF_AH * 2, s);
            cp16(d + OFF_AL * 2, A1 + (s - A0));
        }
        #pragma unroll
        for (int t = 0; t < 2; t++) {
            int i = tid + t * 256;
            int r = i >> 3, sg = i & 7;
            uint32_t d = smb + (uint32_t)(r * PADK + sg * 8) * 2;
            const __nv_bfloat16* s = B0 + (size_t)r * D_ + k0 + sg * 8;
            cp16(d + OFF_BH * 2, s);
            cp16(d + OFF_BL * 2, B1 + (s - B0));
        }
        CP_COMMIT();
        CP_WAIT0();
        __syncthreads();

        #pragma unroll
        for (int ks = 0; ks < 4; ks++) {
            uint32_t ah[2][4], al[2][4], bh[2][4], bl[2][4];
            #pragma unroll
            for (int mf = 0; mf < 2; mf++) {
                uint32_t r = wm * 32 + mf * 16 + (lane & 15);
                uint32_t off = (r * PADK + ks * 16 + aKof) * 2;
                ldsm4(ah[mf], smb + OFF_AH * 2 + off);
                ldsm4(al[mf], smb + OFF_AL * 2 + off);
            }
            #pragma unroll
            for (int bf = 0; bf < 2; bf++) {
                uint32_t r = wn * 32 + bf * 16 + bN;
                uint32_t off = (r * PADK + ks * 16 + bKof) * 2;
                ldsm4(bh[bf], smb + OFF_BH * 2 + off);
                ldsm4(bl[bf], smb + OFF_BL * 2 + off);
            }
            #pragma unroll
            for (int mf = 0; mf < 2; mf++)
                #pragma unroll
                for (int bf = 0; bf < 2; bf++) {
                    mma_bf16(acc[mf][bf * 2 + 0], ah[mf], bh[bf][0], bh[bf][1]);
                    mma_bf16(acc[mf][bf * 2 + 1], ah[mf], bh[bf][2], bh[bf][3]);
                    mma_bf16(acc[mf][bf * 2 + 0], ah[mf], bl[bf][0], bl[bf][1]);
                    mma_bf16(acc[mf][bf * 2 + 1], ah[mf], bl[bf][2], bl[bf][3]);
                    mma_bf16(acc[mf][bf * 2 + 0], al[mf], bh[bf][0], bh[bf][1]);
                    mma_bf16(acc[mf][bf * 2 + 1], al[mf], bh[bf][2], bh[bf][3]);
                }
        }
    }

    // --- epilogue: scatter directly from fragments
    if (mode == 0) {
        int t = bn0 >> 8;
        #pragma unroll
        for (int mf = 0; mf < 2; mf++)
            #pragma unroll
            for (int f = 0; f < 4; f++) {
                int bf = f >> 1, half = f & 1;
                #pragma unroll
                for (int e = 0; e < 4; e++) {
                    int rr = bm + wm * 32 + mf * 16 + (lane >> 2) + (e >> 1) * 8;
                    int cc = bn0 + wn * 32 + bf * 16 + half * 8 + (lane & 3) * 2 + (e & 1);
                    int s = rr >> 8, l = rr & 255;
                    int jj = cc & 255;
                    int h = jj >> 5, ch = jj & 31;
                    size_t dst = (((size_t)(s * H_ + h) * L_) + l) * C_ + ch;
                    float v = acc[mf][f][e];
                    if (t == 0)      g_q[dst] = v * QSCALE;
                    else if (t == 1) g_k[dst] = v;
                    else if (t == 2) g_v[dst] = v;
                    else             g_g[dst] = 1.f / (1.f + fast_exp2(-(v + bias[jj]) * LOG2E));
                }
            }
    } else {
        #pragma unroll
        for (int mf = 0; mf < 2; mf++)
            #pragma unroll
            for (int f = 0; f < 4; f++) {
                int bf = f >> 1, half = f & 1;
                #pragma unroll
                for (int e = 0; e < 4; e++) {
                    int rr = bm + wm * 32 + mf * 16 + (lane >> 2) + (e >> 1) * 8;
                    int cc = bn0 + wn * 32 + bf * 16 + half * 8 + (lane & 3) * 2 + (e & 1);
                    outp[(size_t)rr * D_ + cc] = acc[mf][f][e] + bias[cc];
                }
            }
    }
}

// ---------------- Attention: one block per (s,h), max-free softmax ---------
// float4 smem loads: 16 LDS.128 per key instead of 64 scalar LDS.
__global__ __launch_bounds__(256) void attn_kernel() {
    extern __shared__ float smem[];
    float* ks = smem;
    float* vs = smem + L_ * C_;
    float* bcol = smem + 2 * L_ * C_;
    int sh = blockIdx.x;
    int s = sh >> 3, h = sh & 7;
    size_t base = (size_t)sh * (L_ * C_);
    int tid = threadIdx.x;

    for (int i = tid; i < L_ * C_ / 4; i += 256) {
        ((float4*)ks)[i] = ((const float4*)(g_k + base))[i];
        ((float4*)vs)[i] = ((const float4*)(g_v + base))[i];
    }
    bcol[tid] = (g_rp[tid] != 0.f) ? NEG_BIAS2 : 0.f;
    __syncthreads();

    int l = tid;
    float4 q4[8];
    const float4* qsrc = (const float4*)(g_q + base + (size_t)l * C_);
    #pragma unroll
    for (int c = 0; c < 8; c++) q4[c] = qsrc[c];
    bool rowm = (g_sp[l] != 0.f);

    float ssum = 0.f;
    float4 acc[8];
    #pragma unroll
    for (int c = 0; c < 8; c++) acc[c] = make_float4(0.f, 0.f, 0.f, 0.f);

    for (int j = 0; j < L_; j++) {
        const float4* kr = (const float4*)(ks + j * C_);
        float s0 = 0.f, s1 = 0.f, s2 = 0.f, s3 = 0.f;
        #pragma unroll
        for (int c = 0; c < 8; c++) {
            float4 kv = kr[c];
            s0 = fmaf(q4[c].x, kv.x, s0);
            s1 = fmaf(q4[c].y, kv.y, s1);
            s2 = fmaf(q4[c].z, kv.z, s2);
            s3 = fmaf(q4[c].w, kv.w, s3);
        }
        float sc = (s0 + s1) + (s2 + s3);
        if (!rowm) sc += bcol[j];
        float p = fast_exp2(sc);
        ssum += p;
        const float4* vr = (const float4*)(vs + j * C_);
        #pragma unroll
        for (int c = 0; c < 8; c++) {
            float4 vv = vr[c];
            acc[c].x = fmaf(p, vv.x, acc[c].x);
            acc[c].y = fmaf(p, vv.y, acc[c].y);
            acc[c].z = fmaf(p, vv.z, acc[c].z);
            acc[c].w = fmaf(p, vv.w, acc[c].w);
        }
    }

    float inv = 1.f / ssum;
    size_t obase = ((size_t)(s * L_ + l)) * D_ + h * C_;
    size_t gbase = base + (size_t)l * C_;
    #pragma unroll
    for (int c = 0; c < 8; c++) {
        float o[4] = {acc[c].x, acc[c].y, acc[c].z, acc[c].w};
        #pragma unroll
        for (int e = 0; e < 4; e++) {
            float ov = o[e] * inv * g_g[gbase + c * 4 + e];
            __nv_bfloat16 hi = __float2bfloat16(ov);
            __nv_bfloat16 lo = __float2bfloat16(ov - __bfloat162float(hi));
            g_oh[obase + c * 4 + e] = hi;
            g_ol[obase + c * 4 + e] = lo;
        }
    }
}

// ---------------- launch ---------------------------------------------------
extern "C" void kernel_launch(void* const* d_in, const int* in_sizes, int n_in,
                              void* d_out, int out_size) {
    const float* m    = (const float*)d_in[0];
    const void*  spad = d_in[1];
    const void*  rpad = d_in[2];
    const float* ln_g = (const float*)d_in[3];
    const float* ln_b = (const float*)d_in[4];
    const float* Wq   = (const float*)d_in[5];
    const float* Wk   = (const float*)d_in[6];
    const float* Wv   = (const float*)d_in[7];
    const float* Wg   = (const float*)d_in[8];
    const float* bg   = (const float*)d_in[9];
    const float* Wo   = (const float*)d_in[10];
    const float* bo   = (const float*)d_in[11];
    float* out = (float*)d_out;

    static int smem_set = 0;
    if (!smem_set) {
        cudaFuncSetAttribute(gemm_kernel, cudaFuncAttributeMaxDynamicSharedMemorySize,
                             SM_GEMM_HALVES * 2);
        cudaFuncSetAttribute(attn_kernel, cudaFuncAttributeMaxDynamicSharedMemorySize,
                             (2 * L_ * C_ + L_) * (int)sizeof(float));
        smem_set = 1;
    }

    prep_mask_kernel<<<1, 256>>>(spad, rpad);
    prep_w_kernel<<<5 * 256, 256>>>(Wq, Wk, Wv, Wg, Wo);
    ln_kernel<<<MROWS / 8, 256>>>(m, ln_g, ln_b);

    __nv_bfloat16 *mh, *ml, *wh, *wl, *oh, *ol;
    cudaGetSymbolAddress((void**)&mh, g_mnh);
    cudaGetSymbolAddress((void**)&ml, g_mnl);
    cudaGetSymbolAddress((void**)&wh, g_wh);
    cudaGetSymbolAddress((void**)&wl, g_wl);
    cudaGetSymbolAddress((void**)&oh, g_oh);
    cudaGetSymbolAddress((void**)&ol, g_ol);

    dim3 gp(16, MROWS / 128);   // proj: N = [Wq|Wk|Wv|Wg]
    gemm_kernel<<<gp, 256, SM_GEMM_HALVES * 2>>>(mh, ml, wh, wl, bg, nullptr, 0);

    int attn_smem = (2 * L_ * C_ + L_) * (int)sizeof(float);
    attn_kernel<<<S_ * H_, 256, attn_smem>>>();

    dim3 go(4, MROWS / 128);    // out projection
    gemm_kernel<<<go, 256, SM_GEMM_HALVES * 2>>>(oh, ol, wh + 4 * D_ * D_,
                                                 wl + 4 * D_ * D_, bo, out, 1);
}

// round 13
// speedup vs baseline: 1.0029x; 1.0010x over previous
#include <cuda_runtime.h>
#include <cuda_bf16.h>
#include <cstdint>

// Problem dims (fixed): B=1, S=128, L=256, D=256, H=8, C=32
#define S_ 128
#define L_ 256
#define D_ 256
#define H_ 8
#define C_ 32
#define MROWS (S_ * L_)          // 32768
#define LOG2E 1.4426950408889634f
#define NEG_BIAS2 (-10000.0f * LOG2E)
#define QSCALE (0.17677669529663687f * LOG2E)  // (1/sqrt(32)) * log2(e)

// ---------------- scratch (device globals; no cudaMalloc allowed) ----------
__device__ __nv_bfloat16 g_mnh[MROWS * D_];
__device__ __nv_bfloat16 g_mnl[MROWS * D_];
__device__ __nv_bfloat16 g_wh[5 * D_ * D_];   // [Wq|Wk|Wv|Wg|Wo] hi
__device__ __nv_bfloat16 g_wl[5 * D_ * D_];   // lo
__device__ float g_q[MROWS * D_];    // [s][h][l][c], pre-scaled by QSCALE
__device__ float g_k[MROWS * D_];
__device__ float g_v[MROWS * D_];
__device__ float g_g[MROWS * D_];
__device__ __nv_bfloat16 g_oh[MROWS * D_];    // attn out hi, [s][l][h*32+c]
__device__ __nv_bfloat16 g_ol[MROWS * D_];
__device__ float g_sp[L_];
__device__ float g_rp[L_];

__device__ __forceinline__ float fast_exp2(float x) {
    float y;
    asm("ex2.approx.ftz.f32 %0, %1;" : "=f"(y) : "f"(x));
    return y;
}
__device__ __forceinline__ uint32_t smem_u32(const void* p) {
    uint32_t a;
    asm("{ .reg .u64 t; cvta.to.shared.u64 t, %1; cvt.u32.u64 %0, t; }" : "=r"(a) : "l"(p));
    return a;
}
__device__ __forceinline__ void ldsm4(uint32_t* r, uint32_t addr) {
    asm volatile("ldmatrix.sync.aligned.m8n8.x4.shared.b16 {%0,%1,%2,%3}, [%4];"
                 : "=r"(r[0]), "=r"(r[1]), "=r"(r[2]), "=r"(r[3]) : "r"(addr));
}
__device__ __forceinline__ void mma_bf16(float* c, const uint32_t* a, uint32_t b0,
                                         uint32_t b1) {
    asm volatile(
        "mma.sync.aligned.m16n8k16.row.col.f32.bf16.bf16.f32 "
        "{%0,%1,%2,%3}, {%4,%5,%6,%7}, {%8,%9}, {%0,%1,%2,%3};"
        : "+f"(c[0]), "+f"(c[1]), "+f"(c[2]), "+f"(c[3])
        : "r"(a[0]), "r"(a[1]), "r"(a[2]), "r"(a[3]), "r"(b0), "r"(b1));
}
__device__ __forceinline__ void cp16(uint32_t smaddr, const void* gptr) {
    asm volatile("cp.async.cg.shared.global [%0], [%1], 16;" :: "r"(smaddr), "l"(gptr));
}
#define CP_COMMIT() asm volatile("cp.async.commit_group;" ::: "memory")
#define CP_WAIT0()  asm volatile("cp.async.wait_group 0;" ::: "memory")

// ---------------- mask prep: dtype-agnostic (bool8 / int32 / float32) ------
__global__ void prep_mask_kernel(const void* sp_raw, const void* rp_raw) {
    __shared__ int flagF, flagOff;
    int tid = threadIdx.x;  // 256
    if (tid == 0) { flagF = 0; flagOff = 0; }
    __syncthreads();
    const unsigned char* pb = (const unsigned char*)sp_raw;
    const unsigned char* qb = (const unsigned char*)rp_raw;
    unsigned char b1 = pb[tid], b2 = qb[tid];
    if ((tid & 3) == 3 && (b1 == 0x3F || b2 == 0x3F)) atomicOr(&flagF, 1);
    if ((tid & 3) != 0 && (b1 != 0 || b2 != 0)) atomicOr(&flagOff, 1);
    __syncthreads();
    int mode = flagF ? 2 : (flagOff ? 0 : 1);
    float vs, vr;
    if (mode == 0) {
        vs = (((const unsigned char*)sp_raw)[tid] != 0) ? 1.f : 0.f;
        vr = (((const unsigned char*)rp_raw)[tid] != 0) ? 1.f : 0.f;
    } else if (mode == 1) {
        vs = (((const int*)sp_raw)[tid] != 0) ? 1.f : 0.f;
        vr = (((const int*)rp_raw)[tid] != 0) ? 1.f : 0.f;
    } else {
        vs = (((const float*)sp_raw)[tid] != 0.f) ? 1.f : 0.f;
        vr = (((const float*)rp_raw)[tid] != 0.f) ? 1.f : 0.f;
    }
    g_sp[tid] = vs;
    g_rp[tid] = vr;
}

// ---------------- weight prep: fp32 -> bf16 hi/lo --------------------------
__global__ __launch_bounds__(256) void prep_w_kernel(
    const float* __restrict__ Wq, const float* __restrict__ Wk,
    const float* __restrict__ Wv, const float* __restrict__ Wg,
    const float* __restrict__ Wo) {
    int row = blockIdx.x;      // 0..1279
    int tid = threadIdx.x;
    int t = row >> 8;
    const float* W = (t == 0) ? Wq : (t == 1) ? Wk : (t == 2) ? Wv : (t == 3) ? Wg : Wo;
    float v = W[(size_t)(row & 255) * D_ + tid];
    __nv_bfloat16 hi = __float2bfloat16(v);
    __nv_bfloat16 lo = __float2bfloat16(v - __bfloat162float(hi));
    g_wh[(size_t)row * D_ + tid] = hi;
    g_wl[(size_t)row * D_ + tid] = lo;
}

// ---------------- LayerNorm: warp per row -> bf16 hi/lo --------------------
__global__ __launch_bounds__(256) void ln_kernel(const float* __restrict__ m,
                                                 const float* __restrict__ gam,
                                                 const float* __restrict__ bet) {
    int row = blockIdx.x * 8 + (threadIdx.x >> 5);
    int lane = threadIdx.x & 31;
    const float4* src = (const float4*)(m + (size_t)row * D_);
    float4 a = src[lane], b = src[lane + 32];
    float s1 = a.x + a.y + a.z + a.w + b.x + b.y + b.z + b.w;
    float s2 = a.x * a.x + a.y * a.y + a.z * a.z + a.w * a.w +
               b.x * b.x + b.y * b.y + b.z * b.z + b.w * b.w;
    #pragma unroll
    for (int o = 16; o > 0; o >>= 1) {
        s1 += __shfl_xor_sync(0xFFFFFFFFu, s1, o);
        s2 += __shfl_xor_sync(0xFFFFFFFFu, s2, o);
    }
    float mu = s1 * (1.f / D_);
    float rstd = rsqrtf(s2 * (1.f / D_) - mu * mu + 1e-5f);
    float va[8] = {a.x, a.y, a.z, a.w, b.x, b.y, b.z, b.w};
    #pragma unroll
    for (int i = 0; i < 8; i++) {
        int c = (i < 4) ? (lane * 4 + i) : (128 + lane * 4 + i - 4);
        float y = (va[i] - mu) * rstd * gam[c] + bet[c];
        __nv_bfloat16 hi = __float2bfloat16(y);
        __nv_bfloat16 lo = __float2bfloat16(y - __bfloat162float(hi));
        g_mnh[(size_t)row * D_ + c] = hi;
        g_mnl[(size_t)row * D_ + c] = lo;
    }
}

// ---------------- mma.sync GEMM: C[128x64] = A[128x256] * B[64x256]^T ------
// bf16x3: hi*hi + hi*lo + lo*hi, fp32 accumulators. Fragments loaded ONCE per
// k16 step, all 3 passes run from registers. Warps tiled 4m x 2n (32x32 each).
// 2 CTAs/SM via __launch_bounds__(256,2); cp.async.cg smem fills.
#define PADK 72
#define OFF_AH 0
#define OFF_AL (128 * PADK)
#define OFF_BH (2 * 128 * PADK)
#define OFF_BL (2 * 128 * PADK + 64 * PADK)
#define SM_GEMM_HALVES (2 * 128 * PADK + 2 * 64 * PADK)   // 27648 halves = 55296 B

__global__ __launch_bounds__(256, 2) void gemm_kernel(
    const __nv_bfloat16* __restrict__ Ah, const __nv_bfloat16* __restrict__ Al,
    const __nv_bfloat16* __restrict__ Bh, const __nv_bfloat16* __restrict__ Bl,
    const float* __restrict__ bias, float* __restrict__ outp, int mode) {
    extern __shared__ __align__(16) __nv_bfloat16 sm[];
    uint32_t smb = smem_u32(sm);
    int tid = threadIdx.x;
    int wid = tid >> 5, lane = tid & 31;
    int wm = wid & 3, wn = wid >> 2;
    int bm = blockIdx.y * 128;
    int bn0 = blockIdx.x * 64;

    const __nv_bfloat16* A0 = Ah + (size_t)bm * D_;
    const __nv_bfloat16* A1 = Al + (size_t)bm * D_;
    const __nv_bfloat16* B0 = Bh + (size_t)bn0 * D_;
    const __nv_bfloat16* B1 = Bl + (size_t)bn0 * D_;

    float acc[2][4][4];
    #pragma unroll
    for (int i = 0; i < 2; i++)
        #pragma unroll
        for (int f = 0; f < 4; f++)
            #pragma unroll
            for (int e = 0; e < 4; e++) acc[i][f][e] = 0.f;

    uint32_t aKof = (lane >> 4) * 8;
    uint32_t bN = (lane & 7) + ((lane >> 4) << 3);
    uint32_t bKof = ((lane >> 3) & 1) * 8;

    for (int k0 = 0; k0 < D_; k0 += 64) {
        if (k0) __syncthreads();   // prior chunk's reads done before overwrite
        // fill: A 128x64 hi+lo (1024 x 16B each), B 64x64 hi+lo (512 each)
        #pragma unroll
        for (int t = 0; t < 4; t++) {
            int i = tid + t * 256;
            int r = i >> 3, sg = i & 7;
            uint32_t d = smb + (uint32_t)(r * PADK + sg * 8) * 2;
            const __nv_bfloat16* s = A0 + (size_t)r * D_ + k0 + sg * 8;
            cp16(d + OFF_AH * 2, s);
            cp16(d + OFF_AL * 2, A1 + (s - A0));
        }
        #pragma unroll
        for (int t = 0; t < 2; t++) {
            int i = tid + t * 256;
            int r = i >> 3, sg = i & 7;
            uint32_t d = smb + (uint32_t)(r * PADK + sg * 8) * 2;
            const __nv_bfloat16* s = B0 + (size_t)r * D_ + k0 + sg * 8;
            cp16(d + OFF_BH * 2, s);
            cp16(d + OFF_BL * 2, B1 + (s - B0));
        }
        CP_COMMIT();
        CP_WAIT0();
        __syncthreads();

        #pragma unroll
        for (int ks = 0; ks < 4; ks++) {
            uint32_t ah[2][4], al[2][4], bh[2][4], bl[2][4];
            #pragma unroll
            for (int mf = 0; mf < 2; mf++) {
                uint32_t r = wm * 32 + mf * 16 + (lane & 15);
                uint32_t off = (r * PADK + ks * 16 + aKof) * 2;
                ldsm4(ah[mf], smb + OFF_AH * 2 + off);
                ldsm4(al[mf], smb + OFF_AL * 2 + off);
            }
            #pragma unroll
            for (int bf = 0; bf < 2; bf++) {
                uint32_t r = wn * 32 + bf * 16 + bN;
                uint32_t off = (r * PADK + ks * 16 + bKof) * 2;
                ldsm4(bh[bf], smb + OFF_BH * 2 + off);
                ldsm4(bl[bf], smb + OFF_BL * 2 + off);
            }
            #pragma unroll
            for (int mf = 0; mf < 2; mf++)
                #pragma unroll
                for (int bf = 0; bf < 2; bf++) {
                    mma_bf16(acc[mf][bf * 2 + 0], ah[mf], bh[bf][0], bh[bf][1]);
                    mma_bf16(acc[mf][bf * 2 + 1], ah[mf], bh[bf][2], bh[bf][3]);
                    mma_bf16(acc[mf][bf * 2 + 0], ah[mf], bl[bf][0], bl[bf][1]);
                    mma_bf16(acc[mf][bf * 2 + 1], ah[mf], bl[bf][2], bl[bf][3]);
                    mma_bf16(acc[mf][bf * 2 + 0], al[mf], bh[bf][0], bh[bf][1]);
                    mma_bf16(acc[mf][bf * 2 + 1], al[mf], bh[bf][2], bh[bf][3]);
                }
        }
    }

    // --- epilogue: scatter directly from fragments
    if (mode == 0) {
        int t = bn0 >> 8;
        #pragma unroll
        for (int mf = 0; mf < 2; mf++)
            #pragma unroll
            for (int f = 0; f < 4; f++) {
                int bf = f >> 1, half = f & 1;
                #pragma unroll
                for (int e = 0; e < 4; e++) {
                    int rr = bm + wm * 32 + mf * 16 + (lane >> 2) + (e >> 1) * 8;
                    int cc = bn0 + wn * 32 + bf * 16 + half * 8 + (lane & 3) * 2 + (e & 1);
                    int s = rr >> 8, l = rr & 255;
                    int jj = cc & 255;
                    int h = jj >> 5, ch = jj & 31;
                    size_t dst = (((size_t)(s * H_ + h) * L_) + l) * C_ + ch;
                    float v = acc[mf][f][e];
                    if (t == 0)      g_q[dst] = v * QSCALE;
                    else if (t == 1) g_k[dst] = v;
                    else if (t == 2) g_v[dst] = v;
                    else             g_g[dst] = 1.f / (1.f + fast_exp2(-(v + bias[jj]) * LOG2E));
                }
            }
    } else {
        #pragma unroll
        for (int mf = 0; mf < 2; mf++)
            #pragma unroll
            for (int f = 0; f < 4; f++) {
                int bf = f >> 1, half = f & 1;
                #pragma unroll
                for (int e = 0; e < 4; e++) {
                    int rr = bm + wm * 32 + mf * 16 + (lane >> 2) + (e >> 1) * 8;
                    int cc = bn0 + wn * 32 + bf * 16 + half * 8 + (lane & 3) * 2 + (e & 1);
                    outp[(size_t)rr * D_ + cc] = acc[mf][f][e] + bias[cc];
                }
            }
    }
}

// ---------------- Attention: one block per (s,h), max-free softmax ---------
// float4 smem loads: 16 LDS.128 per key instead of 64 scalar LDS.
__global__ __launch_bounds__(256) void attn_kernel() {
    extern __shared__ float smem[];
    float* ks = smem;
    float* vs = smem + L_ * C_;
    float* bcol = smem + 2 * L_ * C_;
    int sh = blockIdx.x;
    int s = sh >> 3, h = sh & 7;
    size_t base = (size_t)sh * (L_ * C_);
    int tid = threadIdx.x;

    for (int i = tid; i < L_ * C_ / 4; i += 256) {
        ((float4*)ks)[i] = ((const float4*)(g_k + base))[i];
        ((float4*)vs)[i] = ((const float4*)(g_v + base))[i];
    }
    bcol[tid] = (g_rp[tid] != 0.f) ? NEG_BIAS2 : 0.f;
    __syncthreads();

    int l = tid;
    float4 q4[8];
    const float4* qsrc = (const float4*)(g_q + base + (size_t)l * C_);
    #pragma unroll
    for (int c = 0; c < 8; c++) q4[c] = qsrc[c];
    bool rowm = (g_sp[l] != 0.f);

    float ssum = 0.f;
    float4 acc[8];
    #pragma unroll
    for (int c = 0; c < 8; c++) acc[c] = make_float4(0.f, 0.f, 0.f, 0.f);

    for (int j = 0; j < L_; j++) {
        const float4* kr = (const float4*)(ks + j * C_);
        float s0 = 0.f, s1 = 0.f, s2 = 0.f, s3 = 0.f;
        #pragma unroll
        for (int c = 0; c < 8; c++) {
            float4 kv = kr[c];
            s0 = fmaf(q4[c].x, kv.x, s0);
            s1 = fmaf(q4[c].y, kv.y, s1);
            s2 = fmaf(q4[c].z, kv.z, s2);
            s3 = fmaf(q4[c].w, kv.w, s3);
        }
        float sc = (s0 + s1) + (s2 + s3);
        if (!rowm) sc += bcol[j];
        float p = fast_exp2(sc);
        ssum += p;
        const float4* vr = (const float4*)(vs + j * C_);
        #pragma unroll
        for (int c = 0; c < 8; c++) {
            float4 vv = vr[c];
            acc[c].x = fmaf(p, vv.x, acc[c].x);
            acc[c].y = fmaf(p, vv.y, acc[c].y);
            acc[c].z = fmaf(p, vv.z, acc[c].z);
            acc[c].w = fmaf(p, vv.w, acc[c].w);
        }
    }

    float inv = 1.f / ssum;
    size_t obase = ((size_t)(s * L_ + l)) * D_ + h * C_;
    size_t gbase = base + (size_t)l * C_;
    #pragma unroll
    for (int c = 0; c < 8; c++) {
        float o[4] = {acc[c].x, acc[c].y, acc[c].z, acc[c].w};
        #pragma unroll
        for (int e = 0; e < 4; e++) {
            float ov = o[e] * inv * g_g[gbase + c * 4 + e];
            __nv_bfloat16 hi = __float2bfloat16(ov);
            __nv_bfloat16 lo = __float2bfloat16(ov - __bfloat162float(hi));
            g_oh[obase + c * 4 + e] = hi;
            g_ol[obase + c * 4 + e] = lo;
        }
    }
}

// ---------------- launch ---------------------------------------------------
extern "C" void kernel_launch(void* const* d_in, const int* in_sizes, int n_in,
                              void* d_out, int out_size) {
    const float* m    = (const float*)d_in[0];
    const void*  spad = d_in[1];
    const void*  rpad = d_in[2];
    const float* ln_g = (const float*)d_in[3];
    const float* ln_b = (const float*)d_in[4];
    const float* Wq   = (const float*)d_in[5];
    const float* Wk   = (const float*)d_in[6];
    const float* Wv   = (const float*)d_in[7];
    const float* Wg   = (const float*)d_in[8];
    const float* bg   = (const float*)d_in[9];
    const float* Wo   = (const float*)d_in[10];
    const float* bo   = (const float*)d_in[11];
    float* out = (float*)d_out;

    static int smem_set = 0;
    if (!smem_set) {
        cudaFuncSetAttribute(gemm_kernel, cudaFuncAttributeMaxDynamicSharedMemorySize,
                             SM_GEMM_HALVES * 2);
        cudaFuncSetAttribute(attn_kernel, cudaFuncAttributeMaxDynamicSharedMemorySize,
                             (2 * L_ * C_ + L_) * (int)sizeof(float));
        smem_set = 1;
    }

    prep_mask_kernel<<<1, 256>>>(spad, rpad);
    prep_w_kernel<<<5 * 256, 256>>>(Wq, Wk, Wv, Wg, Wo);
    ln_kernel<<<MROWS / 8, 256>>>(m, ln_g, ln_b);

    __nv_bfloat16 *mh, *ml, *wh, *wl, *oh, *ol;
    cudaGetSymbolAddress((void**)&mh, g_mnh);
    cudaGetSymbolAddress((void**)&ml, g_mnl);
    cudaGetSymbolAddress((void**)&wh, g_wh);
    cudaGetSymbolAddress((void**)&wl, g_wl);
    cudaGetSymbolAddress((void**)&oh, g_oh);
    cudaGetSymbolAddress((void**)&ol, g_ol);

    dim3 gp(16, MROWS / 128);   // proj: N = [Wq|Wk|Wv|Wg]
    gemm_kernel<<<gp, 256, SM_GEMM_HALVES * 2>>>(mh, ml, wh, wl, bg, nullptr, 0);

    int attn_smem = (2 * L_ * C_ + L_) * (int)sizeof(float);
    attn_kernel<<<S_ * H_, 256, attn_smem>>>();

    dim3 go(4, MROWS / 128);    // out projection
    gemm_kernel<<<go, 256, SM_GEMM_HALVES * 2>>>(oh, ol, wh + 4 * D_ * D_,
                                                 wl + 4 * D_ * D_, bo, out, 1);
}